// round 7
// baseline (speedup 1.0000x reference)
#include <cuda_runtime.h>
#include <cstdint>

#define BB 8
#define TT 512
#define DD 512
#define VV 32000
#define FOURD 2048
#define NBLK 128

// ---------------- device scratch (no allocations allowed) ----------------
__device__ float g_x  [BB*TT*DD];       // embedded (shifted) input
__device__ float g_xW [BB*TT*FOURD];    // x @ Wx0 + b0 precompute
__device__ float g_h1 [BB*TT*DD];       // layer-0 hidden sequence
__device__ float g_h2 [BB*TT*DD];       // layer-1 hidden sequence
__device__ float g_h2r[BB*TT*DD];       // h2 rounded to tf32
__device__ float g_Wt [(size_t)VV*DD];  // Wout^T [V,512], tf32-rounded
__device__ int   g_prog0[NBLK];         // layer-0 per-CTA progress (steps done)
__device__ int   g_prog1[NBLK];         // layer-1 per-CTA progress

// ---------------- f32x2 helpers (FFMA2: 2x fp32 throughput) ----------------
__device__ __forceinline__ unsigned long long pack2(float lo, float hi) {
    unsigned long long r;
    asm("mov.b64 %0, {%1, %2};" : "=l"(r) : "f"(lo), "f"(hi));
    return r;
}
__device__ __forceinline__ void fma2(unsigned long long &acc,
                                     unsigned long long a, unsigned long long b) {
    asm("fma.rn.f32x2 %0, %1, %2, %0;" : "+l"(acc) : "l"(a), "l"(b));
}
__device__ __forceinline__ float2 unpack2(unsigned long long v) {
    float2 f;
    asm("mov.b64 {%0, %1}, %2;" : "=f"(f.x), "=f"(f.y) : "l"(v));
    return f;
}

// ---------------- small helpers ----------------
__device__ __forceinline__ uint32_t smem_u32(const void* p) {
    uint32_t a;
    asm("{ .reg .u64 t; cvta.to.shared.u64 t, %1; cvt.u32.u64 %0, t; }"
        : "=r"(a) : "l"(p));
    return a;
}
__device__ __forceinline__ float tf32r(float x) {
    uint32_t r;
    asm("cvt.rna.tf32.f32 %0, %1;" : "=r"(r) : "f"(x));
    return __uint_as_float(r);
}
__device__ __forceinline__ int ld_acq(const int* p) {
    int v;
    asm volatile("ld.acquire.gpu.global.b32 %0, [%1];" : "=r"(v) : "l"(p) : "memory");
    return v;
}
__device__ __forceinline__ void st_rel(int* p, int v) {
    asm volatile("st.release.gpu.global.b32 [%0], %1;" :: "l"(p), "r"(v) : "memory");
}
__device__ __forceinline__ void cp_async16(uint32_t dst, const void* src) {
    asm volatile("cp.async.ca.shared.global [%0], [%1], 16;"
                 :: "r"(dst), "l"(src) : "memory");
}
__device__ __forceinline__ void cp_commit() {
    asm volatile("cp.async.commit_group;" ::: "memory");
}
template<int N> __device__ __forceinline__ void cp_wait() {
    asm volatile("cp.async.wait_group %0;" :: "n"(N) : "memory");
}
// mma.sync tf32 m16n8k8 (portable PTX; HMMA on Blackwell)
__device__ __forceinline__ void mma_tf32(float* c, const uint32_t* a, const uint32_t* b) {
    asm volatile(
        "mma.sync.aligned.m16n8k8.row.col.f32.tf32.tf32.f32 "
        "{%0,%1,%2,%3}, {%4,%5,%6,%7}, {%8,%9}, {%0,%1,%2,%3};"
        : "+f"(c[0]), "+f"(c[1]), "+f"(c[2]), "+f"(c[3])
        : "r"(a[0]), "r"(a[1]), "r"(a[2]), "r"(a[3]), "r"(b[0]), "r"(b[1]));
}

// ---------------- embedding + shift-right + progress reset ----------------
// Reference pads TOKEN IDS with 0 then embeds: t=0 uses embed[0].
__global__ void __launch_bounds__(128) embed_kernel(
    const int* __restrict__ tokens, const float* __restrict__ emb,
    float* __restrict__ out)
{
    int row = blockIdx.x;          // row = b*T + t
    int t = row & (TT - 1);
    int tok = (t == 0) ? 0 : tokens[row - 1];
    float4 v = *(const float4*)(emb + (size_t)tok * DD + threadIdx.x * 4);
    *(float4*)(out + (size_t)row * DD + threadIdx.x * 4) = v;
    if (blockIdx.x == 0 && threadIdx.x < NBLK) {
        g_prog0[threadIdx.x] = 0;
        g_prog1[threadIdx.x] = 0;
    }
}

// ---------------- transpose + tf32-round Wout [512,32000] -> Wt [32000,512] ----------------
__global__ void __launch_bounds__(256) transpose_round_kernel(
    const float* __restrict__ W, float* __restrict__ Wt)
{
    __shared__ float tile[32][33];
    int n0 = blockIdx.x * 32, k0 = blockIdx.y * 32;
    int tx = threadIdx.x & 31, ty = threadIdx.x >> 5;  // 32 x 8
    #pragma unroll
    for (int j = 0; j < 4; j++)
        tile[ty + j*8][tx] = W[(size_t)(k0 + ty + j*8) * VV + n0 + tx];
    __syncthreads();
    #pragma unroll
    for (int j = 0; j < 4; j++)
        Wt[(size_t)(n0 + ty + j*8) * DD + k0 + tx] = tf32r(tile[tx][ty + j*8]);
}

// ---------------- tf32 mma.sync GEMM: C[4096,32000] = A @ Bt^T + bias ----------------
#define GSTAGE_B 36864
#define GEMM_SMEM (2*GSTAGE_B)

__global__ void __launch_bounds__(256) gemm_mma_kernel(
    const float* __restrict__ A, const float* __restrict__ Bt,
    const float* __restrict__ bias, float* __restrict__ C)
{
    extern __shared__ char smem[];
    const int tid  = threadIdx.x;
    const int wid  = tid >> 5;
    const int lane = tid & 31;
    const int bx = blockIdx.x, by = blockIdx.y;
    const uint32_t sb = smem_u32(smem);

    const int m0 = (wid >> 2) * 64;
    const int n0 = (wid & 3) * 32;
    const int fr = lane >> 2;
    const int fc = lane & 3;

    const float* Asrc = A  + (size_t)(by * 128) * DD;
    const float* Bsrc = Bt + (size_t)(bx * 128) * DD;

    int lr[4], lc[4];
    #pragma unroll
    for (int i = 0; i < 4; i++) {
        int idx = tid + i * 256;
        lr[i] = idx >> 3;
        lc[i] = (idx & 7) * 4;
    }

    #pragma unroll
    for (int s = 0; s < 2; s++) {
        uint32_t base = sb + s * GSTAGE_B;
        #pragma unroll
        for (int i = 0; i < 4; i++) {
            uint32_t doff = (uint32_t)(lr[i] * 36 + lc[i]) * 4;
            cp_async16(base + doff,             Asrc + (size_t)lr[i] * DD + s * 32 + lc[i]);
            cp_async16(base + 18432 + doff,     Bsrc + (size_t)lr[i] * DD + s * 32 + lc[i]);
        }
        cp_commit();
    }

    float acc[4][4][4];
    #pragma unroll
    for (int mt = 0; mt < 4; mt++)
        #pragma unroll
        for (int nt = 0; nt < 4; nt++)
            #pragma unroll
            for (int j = 0; j < 4; j++) acc[mt][nt][j] = 0.f;

    for (int s = 0; s < 16; s++) {
        if (s < 15) cp_wait<1>(); else cp_wait<0>();
        __syncthreads();

        const uint32_t* Au = (const uint32_t*)(smem + (s & 1) * GSTAGE_B);
        const uint32_t* Bu = Au + 4608;

        #pragma unroll
        for (int kb = 0; kb < 4; kb++) {
            const int kc = kb * 8;
            uint32_t af[4][4], bf[4][2];
            #pragma unroll
            for (int mt = 0; mt < 4; mt++) {
                const uint32_t* ap = Au + (m0 + mt * 16 + fr) * 36 + kc + fc;
                af[mt][0] = ap[0];
                af[mt][1] = ap[8 * 36];
                af[mt][2] = ap[4];
                af[mt][3] = ap[8 * 36 + 4];
            }
            #pragma unroll
            for (int nt = 0; nt < 4; nt++) {
                const uint32_t* bp = Bu + (n0 + nt * 8 + fr) * 36 + kc + fc;
                bf[nt][0] = bp[0];
                bf[nt][1] = bp[4];
            }
            #pragma unroll
            for (int mt = 0; mt < 4; mt++)
                #pragma unroll
                for (int nt = 0; nt < 4; nt++)
                    mma_tf32(acc[mt][nt], af[mt], bf[nt]);
        }
        __syncthreads();

        if (s + 2 < 16) {
            uint32_t base = sb + (s & 1) * GSTAGE_B;
            const int k0 = (s + 2) * 32;
            #pragma unroll
            for (int i = 0; i < 4; i++) {
                uint32_t doff = (uint32_t)(lr[i] * 36 + lc[i]) * 4;
                cp_async16(base + doff,         Asrc + (size_t)lr[i] * DD + k0 + lc[i]);
                cp_async16(base + 18432 + doff, Bsrc + (size_t)lr[i] * DD + k0 + lc[i]);
            }
            cp_commit();
        }
    }

    const int colbase = bx * 128 + n0;
    float2 bv[4];
    #pragma unroll
    for (int nt = 0; nt < 4; nt++)
        bv[nt] = *(const float2*)&bias[colbase + nt * 8 + 2 * fc];
    #pragma unroll
    for (int mt = 0; mt < 4; mt++) {
        const size_t r0 = (size_t)(by * 128 + m0 + mt * 16 + fr);
        #pragma unroll
        for (int nt = 0; nt < 4; nt++) {
            const size_t coff = (size_t)(colbase + nt * 8 + 2 * fc);
            float2 v0 = make_float2(acc[mt][nt][0] + bv[nt].x,
                                    acc[mt][nt][1] + bv[nt].y);
            float2 v1 = make_float2(acc[mt][nt][2] + bv[nt].x,
                                    acc[mt][nt][3] + bv[nt].y);
            *(float2*)(C + r0 * VV + coff)       = v0;
            *(float2*)(C + (r0 + 8) * VV + coff) = v1;
        }
    }
}

// ---------------- fp32 SGEMM with f32x2 (layer-0 input GEMM) ----------------
__global__ void __launch_bounds__(256) sgemm_f32x2(
    const float* __restrict__ A, const float* __restrict__ W,
    const float* __restrict__ bias, float* __restrict__ C,
    int M, int N, int K)
{
    __shared__ float As[16][132];
    __shared__ float Bs[16][128];

    const int tid  = threadIdx.x;
    const int trow = tid >> 4;
    const int tcol = tid & 15;
    const int bx = blockIdx.x, by = blockIdx.y;

    unsigned long long acc[8][4];
    #pragma unroll
    for (int i = 0; i < 8; i++)
        #pragma unroll
        for (int j = 0; j < 4; j++) acc[i][j] = 0ull;

    const float* Ap = A + (size_t)(by * 128) * K;
    const float* Bp = W + (size_t)(bx * 128);

    for (int kt = 0; kt < K; kt += 16) {
        #pragma unroll
        for (int l = 0; l < 2; l++) {
            int idx = tid + l * 256;
            int r  = idx >> 2;
            int kv = (idx & 3) * 4;
            float4 a = *(const float4*)(Ap + (size_t)r * K + kt + kv);
            As[kv + 0][r] = a.x; As[kv + 1][r] = a.y;
            As[kv + 2][r] = a.z; As[kv + 3][r] = a.w;
            int kr = idx >> 5;
            int cv = (idx & 31) * 4;
            *(float4*)&Bs[kr][cv] =
                *(const float4*)(Bp + (size_t)(kt + kr) * N + cv);
        }
        __syncthreads();
        #pragma unroll
        for (int k = 0; k < 16; k++) {
            float4 a0 = *(float4*)&As[k][trow * 8];
            float4 a1 = *(float4*)&As[k][trow * 8 + 4];
            ulonglong2 b0 = *(ulonglong2*)&Bs[k][tcol * 8];
            ulonglong2 b1 = *(ulonglong2*)&Bs[k][tcol * 8 + 4];
            unsigned long long bb[4] = { b0.x, b0.y, b1.x, b1.y };
            float av[8] = { a0.x, a0.y, a0.z, a0.w, a1.x, a1.y, a1.z, a1.w };
            #pragma unroll
            for (int i = 0; i < 8; i++) {
                unsigned long long a2 = pack2(av[i], av[i]);
                #pragma unroll
                for (int j = 0; j < 4; j++) fma2(acc[i][j], a2, bb[j]);
            }
        }
        __syncthreads();
    }

    const int c0 = bx * 128 + tcol * 8;
    float bsv[8];
    #pragma unroll
    for (int j = 0; j < 8; j++) bsv[j] = bias[c0 + j];
    #pragma unroll
    for (int i = 0; i < 8; i++) {
        int r = by * 128 + trow * 8 + i;
        float ov[8];
        #pragma unroll
        for (int j = 0; j < 4; j++) {
            float2 f = unpack2(acc[i][j]);
            ov[2*j]   = f.x + bsv[2*j];
            ov[2*j+1] = f.y + bsv[2*j+1];
        }
        float* cp = C + (size_t)r * N + c0;
        *(float4*)(cp)     = make_float4(ov[0], ov[1], ov[2], ov[3]);
        *(float4*)(cp + 4) = make_float4(ov[4], ov[5], ov[6], ov[7]);
    }
}

// ---------------- pipelined 2-layer persistent LSTM recurrence ----------------
// 256 CTAs x 128 threads, 2 CTAs/SM (103040 B smem each), all co-resident.
// blk 0..127   -> layer 0 (Wh0, reads precomputed xW0, writes h1, flags g_prog0)
// blk 128..255 -> layer 1 (Wh1+Wx1 in smem, reads h1 pipelined, writes h2+h2r,
//                          flags g_prog1). Layer 1 trails layer 0 by one step.
// SMEM layout:
//   w_s  @ 0      : float[1024][16]  (rows 0-511 Wh, rows 512-1023 Wx; L0 uses 0-511)
//   h_d  @ 65536  : u64 [8][512]    ((h,h)-duplicated vector buffer, reused per phase)
//   red  @ 98304  : float[8][128]
//   gs   @ 102400 : float[128]
//   c_s  @ 102912 : float[32]
#define LSTM_SMEM 103040

__device__ __forceinline__ void load_hdup(unsigned long long (*h_d)[512],
    const float* __restrict__ src, int tt, int w, int lane)
{
    #pragma unroll
    for (int bb2 = 0; bb2 < 2; bb2++) {
        int b = w * 2 + bb2;
        const float* hp = src + ((size_t)(b * TT + tt)) * DD;
        #pragma unroll
        for (int j = 0; j < 8; j++) {
            int k = j * 64 + lane * 2;
            float2 hv = *(const float2*)(hp + k);
            ulonglong2 pv;
            pv.x = pack2(hv.x, hv.x);
            pv.y = pack2(hv.y, hv.y);
            *(ulonglong2*)&h_d[b][k] = pv;
        }
    }
}

__device__ __forceinline__ void matvec_acc(const float (*w_s)[16],
    const unsigned long long (*h_d)[512], int rowoff,
    int w, int kp, int bq, int cq, unsigned long long acc[2][2])
{
    const unsigned long long* h0 = h_d[bq];
    const unsigned long long* h1p = h_d[bq + 4];
    const int kbase = w * 128 + kp;
    #pragma unroll 8
    for (int i = 0; i < 64; i++) {
        int k = kbase + i * 2;
        ulonglong2 wv = *(const ulonglong2*)&w_s[rowoff + k][cq * 4];
        unsigned long long hp0 = h0[k];
        unsigned long long hp1 = h1p[k];
        fma2(acc[0][0], hp0, wv.x);
        fma2(acc[0][1], hp0, wv.y);
        fma2(acc[1][0], hp1, wv.x);
        fma2(acc[1][1], hp1, wv.y);
    }
}

__global__ void __launch_bounds__(128) lstm2_kernel(
    const float* __restrict__ xW0, const float* __restrict__ Wh0,
    const float* __restrict__ Wx1, const float* __restrict__ Wh1,
    const float* __restrict__ b1,
    float* __restrict__ h1g, float* __restrict__ h2g, float* __restrict__ h2rg)
{
    extern __shared__ char smem[];
    float (*w_s)[16] = (float(*)[16])smem;
    unsigned long long (*h_d)[512] = (unsigned long long(*)[512])(smem + 65536);
    float (*red)[128] = (float(*)[128])(smem + 98304);
    float* gs  = (float*)(smem + 102400);
    float* c_s = (float*)(smem + 102912);

    const int tid = threadIdx.x;
    const int L   = blockIdx.x >> 7;       // layer 0 or 1
    const int sub = blockIdx.x & 127;      // CTA within layer

    const int w    = tid >> 5;
    const int lane = tid & 31;
    const int kp = lane >> 4;
    const int bq = (lane >> 2) & 3;
    const int cq = lane & 3;
    const int ob = tid >> 4, oc = tid & 15;
    const int gcol_t = (oc >> 2) * DD + sub * 4 + (oc & 3);  // this thread's gate column

    // ---- load weight slices ----
    if (L == 0) {
        for (int idx = tid; idx < 512 * 16; idx += 128) {
            int k = idx >> 4, c = idx & 15;
            int gcol = (c >> 2) * DD + sub * 4 + (c & 3);
            w_s[k][c] = Wh0[(size_t)k * FOURD + gcol];
        }
    } else {
        for (int idx = tid; idx < 512 * 16; idx += 128) {
            int k = idx >> 4, c = idx & 15;
            int gcol = (c >> 2) * DD + sub * 4 + (c & 3);
            w_s[k][c]       = Wh1[(size_t)k * FOURD + gcol];
            w_s[512 + k][c] = Wx1[(size_t)k * FOURD + gcol];
        }
    }
    float bias_r = (L == 1) ? b1[gcol_t] : 0.f;
    if (tid < 32) c_s[tid] = 0.f;
    __syncthreads();

    if (L == 0) {
        // ================= layer 0 =================
        const size_t xw_coloff = (size_t)gcol_t;
        for (int t = 0; t < TT; t++) {
            float xwv = xW0[((size_t)(ob * TT + t)) * FOURD + xw_coloff];

            unsigned long long acc[2][2] = { {0ull,0ull}, {0ull,0ull} };
            if (t > 0) {
                while (ld_acq(&g_prog0[tid]) < t) { }
                __syncthreads();
                load_hdup(h_d, h1g, t - 1, w, lane);
                __syncthreads();
                matvec_acc(w_s, h_d, 0, w, kp, bq, cq, acc);
            }

            // reduce partials
            {
                int rw = w * 2 + kp;
                #pragma unroll
                for (int bi = 0; bi < 2; bi++)
                    #pragma unroll
                    for (int pj = 0; pj < 2; pj++)
                        *(unsigned long long*)&red[rw][(bq + bi*4) * 16 + cq*4 + pj*2] = acc[bi][pj];
            }
            __syncthreads();
            {
                float s = 0.f;
                #pragma unroll
                for (int r = 0; r < 8; r++) s += red[r][tid];
                gs[tid] = s + xwv;
            }
            __syncthreads();

            if (tid < 32) {
                int b = tid >> 2, dd = tid & 3;
                float iv = gs[b*16 + dd],      fv = gs[b*16 + 4 + dd];
                float gv = gs[b*16 + 8 + dd],  ov = gs[b*16 + 12 + dd];
                float ig = 1.f / (1.f + __expf(-iv));
                float fg = 1.f / (1.f + __expf(-fv));
                float gg = tanhf(gv);
                float og = 1.f / (1.f + __expf(-ov));
                float cc = fg * c_s[tid] + ig * gg;
                c_s[tid] = cc;
                float hh = og * tanhf(cc);
                h1g[((size_t)(b * TT + t)) * DD + sub * 4 + dd] = hh;
            }
            __threadfence();
            __syncthreads();
            if (tid == 0) st_rel(&g_prog0[sub], t + 1);
        }
    } else {
        // ================= layer 1 (trails layer 0) =================
        for (int t = 0; t < TT; t++) {
            unsigned long long acc[2][2] = { {0ull,0ull}, {0ull,0ull} };

            // phase A (non-critical): xW contribution from h1[t]
            while (ld_acq(&g_prog0[tid]) < t + 1) { }
            __syncthreads();
            load_hdup(h_d, h1g, t, w, lane);
            __syncthreads();
            matvec_acc(w_s, h_d, 512, w, kp, bq, cq, acc);   // Wx1 rows
            __syncthreads();   // h_d reuse barrier

            // phase B (critical): recurrent contribution from h2[t-1]
            if (t > 0) {
                while (ld_acq(&g_prog1[tid]) < t) { }
                __syncthreads();
                load_hdup(h_d, h2g, t - 1, w, lane);
                __syncthreads();
                matvec_acc(w_s, h_d, 0, w, kp, bq, cq, acc); // Wh1 rows
            }

            {
                int rw = w * 2 + kp;
                #pragma unroll
                for (int bi = 0; bi < 2; bi++)
                    #pragma unroll
                    for (int pj = 0; pj < 2; pj++)
                        *(unsigned long long*)&red[rw][(bq + bi*4) * 16 + cq*4 + pj*2] = acc[bi][pj];
            }
            __syncthreads();
            {
                float s = 0.f;
                #pragma unroll
                for (int r = 0; r < 8; r++) s += red[r][tid];
                gs[tid] = s + bias_r;
            }
            __syncthreads();

            if (tid < 32) {
                int b = tid >> 2, dd = tid & 3;
                float iv = gs[b*16 + dd],      fv = gs[b*16 + 4 + dd];
                float gv = gs[b*16 + 8 + dd],  ov = gs[b*16 + 12 + dd];
                float ig = 1.f / (1.f + __expf(-iv));
                float fg = 1.f / (1.f + __expf(-fv));
                float gg = tanhf(gv);
                float og = 1.f / (1.f + __expf(-ov));
                float cc = fg * c_s[tid] + ig * gg;
                c_s[tid] = cc;
                float hh = og * tanhf(cc);
                size_t oidx = ((size_t)(b * TT + t)) * DD + sub * 4 + dd;
                h2g[oidx]  = hh;
                h2rg[oidx] = tf32r(hh);
            }
            __threadfence();
            __syncthreads();
            if (tid == 0) st_rel(&g_prog1[sub], t + 1);
        }
    }
}

// ---------------- launch ----------------
extern "C" void kernel_launch(void* const* d_in, const int* in_sizes, int n_in,
                              void* d_out, int out_size)
{
    const int*   tokens = (const int*)d_in[0];
    const float* emb    = (const float*)d_in[1];
    const float* Wx0    = (const float*)d_in[2];
    const float* Wh0    = (const float*)d_in[3];
    const float* b0     = (const float*)d_in[4];
    const float* Wx1    = (const float*)d_in[5];
    const float* Wh1    = (const float*)d_in[6];
    const float* b1     = (const float*)d_in[7];
    const float* Wout   = (const float*)d_in[8];
    const float* bout   = (const float*)d_in[9];
    float* out = (float*)d_out;

    float *gx, *gxw, *gh1, *gh2, *gh2r, *gwt;
    cudaGetSymbolAddress((void**)&gx,   g_x);
    cudaGetSymbolAddress((void**)&gxw,  g_xW);
    cudaGetSymbolAddress((void**)&gh1,  g_h1);
    cudaGetSymbolAddress((void**)&gh2,  g_h2);
    cudaGetSymbolAddress((void**)&gh2r, g_h2r);
    cudaGetSymbolAddress((void**)&gwt,  g_Wt);

    cudaFuncSetAttribute((const void*)lstm2_kernel,
                         cudaFuncAttributeMaxDynamicSharedMemorySize, LSTM_SMEM);
    cudaFuncSetAttribute((const void*)gemm_mma_kernel,
                         cudaFuncAttributeMaxDynamicSharedMemorySize, GEMM_SMEM);

    // 0) transpose+round Wout -> Wt [V,512]
    transpose_round_kernel<<<dim3(VV / 32, DD / 32), 256>>>(Wout, gwt);
    // 1) embedding + shift (+ progress reset)
    embed_kernel<<<BB * TT, 128>>>(tokens, emb, gx);
    // 2) layer 0 input GEMM: xW0 = x @ Wx0 + b0
    sgemm_f32x2<<<dim3(FOURD / 128, (BB * TT) / 128), 256>>>(gx, Wx0, b0, gxw,
                                                             BB * TT, FOURD, DD);
    // 3) pipelined 2-layer recurrence (layer-1 input GEMM folded in)
    lstm2_kernel<<<2 * NBLK, 128, LSTM_SMEM>>>(gxw, Wh0, Wx1, Wh1, b1,
                                               gh1, gh2, gh2r);
    // 4) logits = h2 @ Wout + bout via mma.sync tf32
    gemm_mma_kernel<<<dim3(VV / 128, (BB * TT) / 128), 256, GEMM_SMEM>>>(
        gh2r, gwt, bout, out);
}

// round 8
// speedup vs baseline: 1.1594x; 1.1594x over previous
#include <cuda_runtime.h>
#include <cstdint>

#define BB 8
#define TT 512
#define DD 512
#define VV 32000
#define FOURD 2048
#define NBLK 128

// ---------------- device scratch (no allocations allowed) ----------------
__device__ float g_x  [BB*TT*DD];       // embedded (shifted) input
__device__ float g_xW [BB*TT*FOURD];    // x @ Wx0 + b0 precompute
__device__ float g_h1 [BB*TT*DD];       // layer-0 hidden sequence
__device__ float g_h2 [BB*TT*DD];       // layer-1 hidden sequence
__device__ float g_h2r[BB*TT*DD];       // h2 rounded to tf32
__device__ float g_Wt [(size_t)VV*DD];  // Wout^T [V,512], tf32-rounded
__device__ int   g_prog0[NBLK];         // layer-0 per-CTA progress (steps done)
__device__ int   g_prog1[NBLK];         // layer-1 per-CTA progress

// ---------------- f32x2 helpers (FFMA2: 2x fp32 throughput) ----------------
__device__ __forceinline__ unsigned long long pack2(float lo, float hi) {
    unsigned long long r;
    asm("mov.b64 %0, {%1, %2};" : "=l"(r) : "f"(lo), "f"(hi));
    return r;
}
__device__ __forceinline__ void fma2(unsigned long long &acc,
                                     unsigned long long a, unsigned long long b) {
    asm("fma.rn.f32x2 %0, %1, %2, %0;" : "+l"(acc) : "l"(a), "l"(b));
}
__device__ __forceinline__ float2 unpack2(unsigned long long v) {
    float2 f;
    asm("mov.b64 {%0, %1}, %2;" : "=f"(f.x), "=f"(f.y) : "l"(v));
    return f;
}

// ---------------- small helpers ----------------
__device__ __forceinline__ uint32_t smem_u32(const void* p) {
    uint32_t a;
    asm("{ .reg .u64 t; cvta.to.shared.u64 t, %1; cvt.u32.u64 %0, t; }"
        : "=r"(a) : "l"(p));
    return a;
}
__device__ __forceinline__ float tf32r(float x) {
    uint32_t r;
    asm("cvt.rna.tf32.f32 %0, %1;" : "=r"(r) : "f"(x));
    return __uint_as_float(r);
}
__device__ __forceinline__ int ld_acq(const int* p) {
    int v;
    asm volatile("ld.acquire.gpu.global.b32 %0, [%1];" : "=r"(v) : "l"(p) : "memory");
    return v;
}
__device__ __forceinline__ void st_rel(int* p, int v) {
    asm volatile("st.release.gpu.global.b32 [%0], %1;" :: "l"(p), "r"(v) : "memory");
}
__device__ __forceinline__ void cp_async16(uint32_t dst, const void* src) {
    asm volatile("cp.async.ca.shared.global [%0], [%1], 16;"
                 :: "r"(dst), "l"(src) : "memory");
}
__device__ __forceinline__ void cp_commit() {
    asm volatile("cp.async.commit_group;" ::: "memory");
}
template<int N> __device__ __forceinline__ void cp_wait() {
    asm volatile("cp.async.wait_group %0;" :: "n"(N) : "memory");
}
#define BAR_SYNC(id) asm volatile("bar.sync %0, 128;" :: "r"(id) : "memory")

// mma.sync tf32 m16n8k8 (portable PTX; HMMA on Blackwell)
__device__ __forceinline__ void mma_tf32(float* c, const uint32_t* a, const uint32_t* b) {
    asm volatile(
        "mma.sync.aligned.m16n8k8.row.col.f32.tf32.tf32.f32 "
        "{%0,%1,%2,%3}, {%4,%5,%6,%7}, {%8,%9}, {%0,%1,%2,%3};"
        : "+f"(c[0]), "+f"(c[1]), "+f"(c[2]), "+f"(c[3])
        : "r"(a[0]), "r"(a[1]), "r"(a[2]), "r"(a[3]), "r"(b[0]), "r"(b[1]));
}

// ---------------- embedding + shift-right + progress reset ----------------
// Reference pads TOKEN IDS with 0 then embeds: t=0 uses embed[0].
__global__ void __launch_bounds__(128) embed_kernel(
    const int* __restrict__ tokens, const float* __restrict__ emb,
    float* __restrict__ out)
{
    int row = blockIdx.x;          // row = b*T + t
    int t = row & (TT - 1);
    int tok = (t == 0) ? 0 : tokens[row - 1];
    float4 v = *(const float4*)(emb + (size_t)tok * DD + threadIdx.x * 4);
    *(float4*)(out + (size_t)row * DD + threadIdx.x * 4) = v;
    if (blockIdx.x == 0 && threadIdx.x < NBLK) {
        g_prog0[threadIdx.x] = 0;
        g_prog1[threadIdx.x] = 0;
    }
}

// ---------------- transpose + tf32-round Wout [512,32000] -> Wt [32000,512] ----------------
__global__ void __launch_bounds__(256) transpose_round_kernel(
    const float* __restrict__ W, float* __restrict__ Wt)
{
    __shared__ float tile[32][33];
    int n0 = blockIdx.x * 32, k0 = blockIdx.y * 32;
    int tx = threadIdx.x & 31, ty = threadIdx.x >> 5;  // 32 x 8
    #pragma unroll
    for (int j = 0; j < 4; j++)
        tile[ty + j*8][tx] = W[(size_t)(k0 + ty + j*8) * VV + n0 + tx];
    __syncthreads();
    #pragma unroll
    for (int j = 0; j < 4; j++)
        Wt[(size_t)(n0 + ty + j*8) * DD + k0 + tx] = tf32r(tile[tx][ty + j*8]);
}

// ---------------- tf32 mma.sync GEMM: C[4096,32000] = A @ Bt^T + bias ----------------
#define GSTAGE_B 36864
#define GEMM_SMEM (2*GSTAGE_B)

__global__ void __launch_bounds__(256) gemm_mma_kernel(
    const float* __restrict__ A, const float* __restrict__ Bt,
    const float* __restrict__ bias, float* __restrict__ C)
{
    extern __shared__ char smem[];
    const int tid  = threadIdx.x;
    const int wid  = tid >> 5;
    const int lane = tid & 31;
    const int bx = blockIdx.x, by = blockIdx.y;
    const uint32_t sb = smem_u32(smem);

    const int m0 = (wid >> 2) * 64;
    const int n0 = (wid & 3) * 32;
    const int fr = lane >> 2;
    const int fc = lane & 3;

    const float* Asrc = A  + (size_t)(by * 128) * DD;
    const float* Bsrc = Bt + (size_t)(bx * 128) * DD;

    int lr[4], lc[4];
    #pragma unroll
    for (int i = 0; i < 4; i++) {
        int idx = tid + i * 256;
        lr[i] = idx >> 3;
        lc[i] = (idx & 7) * 4;
    }

    #pragma unroll
    for (int s = 0; s < 2; s++) {
        uint32_t base = sb + s * GSTAGE_B;
        #pragma unroll
        for (int i = 0; i < 4; i++) {
            uint32_t doff = (uint32_t)(lr[i] * 36 + lc[i]) * 4;
            cp_async16(base + doff,             Asrc + (size_t)lr[i] * DD + s * 32 + lc[i]);
            cp_async16(base + 18432 + doff,     Bsrc + (size_t)lr[i] * DD + s * 32 + lc[i]);
        }
        cp_commit();
    }

    float acc[4][4][4];
    #pragma unroll
    for (int mt = 0; mt < 4; mt++)
        #pragma unroll
        for (int nt = 0; nt < 4; nt++)
            #pragma unroll
            for (int j = 0; j < 4; j++) acc[mt][nt][j] = 0.f;

    for (int s = 0; s < 16; s++) {
        if (s < 15) cp_wait<1>(); else cp_wait<0>();
        __syncthreads();

        const uint32_t* Au = (const uint32_t*)(smem + (s & 1) * GSTAGE_B);
        const uint32_t* Bu = Au + 4608;

        #pragma unroll
        for (int kb = 0; kb < 4; kb++) {
            const int kc = kb * 8;
            uint32_t af[4][4], bf[4][2];
            #pragma unroll
            for (int mt = 0; mt < 4; mt++) {
                const uint32_t* ap = Au + (m0 + mt * 16 + fr) * 36 + kc + fc;
                af[mt][0] = ap[0];
                af[mt][1] = ap[8 * 36];
                af[mt][2] = ap[4];
                af[mt][3] = ap[8 * 36 + 4];
            }
            #pragma unroll
            for (int nt = 0; nt < 4; nt++) {
                const uint32_t* bp = Bu + (n0 + nt * 8 + fr) * 36 + kc + fc;
                bf[nt][0] = bp[0];
                bf[nt][1] = bp[4];
            }
            #pragma unroll
            for (int mt = 0; mt < 4; mt++)
                #pragma unroll
                for (int nt = 0; nt < 4; nt++)
                    mma_tf32(acc[mt][nt], af[mt], bf[nt]);
        }
        __syncthreads();

        if (s + 2 < 16) {
            uint32_t base = sb + (s & 1) * GSTAGE_B;
            const int k0 = (s + 2) * 32;
            #pragma unroll
            for (int i = 0; i < 4; i++) {
                uint32_t doff = (uint32_t)(lr[i] * 36 + lc[i]) * 4;
                cp_async16(base + doff,         Asrc + (size_t)lr[i] * DD + k0 + lc[i]);
                cp_async16(base + 18432 + doff, Bsrc + (size_t)lr[i] * DD + k0 + lc[i]);
            }
            cp_commit();
        }
    }

    const int colbase = bx * 128 + n0;
    float2 bv[4];
    #pragma unroll
    for (int nt = 0; nt < 4; nt++)
        bv[nt] = *(const float2*)&bias[colbase + nt * 8 + 2 * fc];
    #pragma unroll
    for (int mt = 0; mt < 4; mt++) {
        const size_t r0 = (size_t)(by * 128 + m0 + mt * 16 + fr);
        #pragma unroll
        for (int nt = 0; nt < 4; nt++) {
            const size_t coff = (size_t)(colbase + nt * 8 + 2 * fc);
            float2 v0 = make_float2(acc[mt][nt][0] + bv[nt].x,
                                    acc[mt][nt][1] + bv[nt].y);
            float2 v1 = make_float2(acc[mt][nt][2] + bv[nt].x,
                                    acc[mt][nt][3] + bv[nt].y);
            *(float2*)(C + r0 * VV + coff)       = v0;
            *(float2*)(C + (r0 + 8) * VV + coff) = v1;
        }
    }
}

// ---------------- fp32 SGEMM with f32x2 (layer-0 input GEMM) ----------------
__global__ void __launch_bounds__(256) sgemm_f32x2(
    const float* __restrict__ A, const float* __restrict__ W,
    const float* __restrict__ bias, float* __restrict__ C,
    int M, int N, int K)
{
    __shared__ float As[16][132];
    __shared__ float Bs[16][128];

    const int tid  = threadIdx.x;
    const int trow = tid >> 4;
    const int tcol = tid & 15;
    const int bx = blockIdx.x, by = blockIdx.y;

    unsigned long long acc[8][4];
    #pragma unroll
    for (int i = 0; i < 8; i++)
        #pragma unroll
        for (int j = 0; j < 4; j++) acc[i][j] = 0ull;

    const float* Ap = A + (size_t)(by * 128) * K;
    const float* Bp = W + (size_t)(bx * 128);

    for (int kt = 0; kt < K; kt += 16) {
        #pragma unroll
        for (int l = 0; l < 2; l++) {
            int idx = tid + l * 256;
            int r  = idx >> 2;
            int kv = (idx & 3) * 4;
            float4 a = *(const float4*)(Ap + (size_t)r * K + kt + kv);
            As[kv + 0][r] = a.x; As[kv + 1][r] = a.y;
            As[kv + 2][r] = a.z; As[kv + 3][r] = a.w;
            int kr = idx >> 5;
            int cv = (idx & 31) * 4;
            *(float4*)&Bs[kr][cv] =
                *(const float4*)(Bp + (size_t)(kt + kr) * N + cv);
        }
        __syncthreads();
        #pragma unroll
        for (int k = 0; k < 16; k++) {
            float4 a0 = *(float4*)&As[k][trow * 8];
            float4 a1 = *(float4*)&As[k][trow * 8 + 4];
            ulonglong2 b0 = *(ulonglong2*)&Bs[k][tcol * 8];
            ulonglong2 b1 = *(ulonglong2*)&Bs[k][tcol * 8 + 4];
            unsigned long long bb[4] = { b0.x, b0.y, b1.x, b1.y };
            float av[8] = { a0.x, a0.y, a0.z, a0.w, a1.x, a1.y, a1.z, a1.w };
            #pragma unroll
            for (int i = 0; i < 8; i++) {
                unsigned long long a2 = pack2(av[i], av[i]);
                #pragma unroll
                for (int j = 0; j < 4; j++) fma2(acc[i][j], a2, bb[j]);
            }
        }
        __syncthreads();
    }

    const int c0 = bx * 128 + tcol * 8;
    float bsv[8];
    #pragma unroll
    for (int j = 0; j < 8; j++) bsv[j] = bias[c0 + j];
    #pragma unroll
    for (int i = 0; i < 8; i++) {
        int r = by * 128 + trow * 8 + i;
        float ov[8];
        #pragma unroll
        for (int j = 0; j < 4; j++) {
            float2 f = unpack2(acc[i][j]);
            ov[2*j]   = f.x + bsv[2*j];
            ov[2*j+1] = f.y + bsv[2*j+1];
        }
        float* cp = C + (size_t)r * N + c0;
        *(float4*)(cp)     = make_float4(ov[0], ov[1], ov[2], ov[3]);
        *(float4*)(cp + 4) = make_float4(ov[4], ov[5], ov[6], ov[7]);
    }
}

// ---------------- warp-specialized pipelined 2-layer LSTM recurrence ----------------
// 256 CTAs x 256 threads, <=2 CTAs/SM (107392 B smem each: 2x = 214784 <= 228KB/SM),
// all 256 co-resident in wave 1 (capacity 296) -> spin-sync is deadlock-safe.
// blk 0..127   -> layer 0: all 8 warps on the Wh0 matvec (k-split 8).
// blk 128..255 -> layer 1: warps 0-3 = phase B (critical, Wh1 x h2[t-1]),
//                          warps 4-7 = phase A (Wx1 x h1[t]) CONCURRENT in the
//                          same window; join at one __syncthreads before reduce.
// h stored plain fp32 in smem, rows padded to 516 floats -> the 8 (kp,bq) LDS.32
// addresses per warp-iter land in 8 distinct banks (conflict-free; the old
// (h,h)-dup layout had a 4-way conflict).
// SMEM: w_s@0 (64KB: rows 0-511 Wh, 512-1023 Wx), h_sB@65536 (16512B),
//       h_sA@82048 (16512B), red@98560 (16x128 f), gs@106752, c_s@107264.
#define LSTM_SMEM 107392

template<int ITERS>
__device__ __forceinline__ void matvec_sm(const float* __restrict__ wrow,
    const float* __restrict__ h_s, int kbase, int cq, int bq,
    unsigned long long acc[2][2])
{
    #pragma unroll 8
    for (int i = 0; i < ITERS; i++) {
        int k = kbase + i * 2;
        ulonglong2 wv = *(const ulonglong2*)(wrow + k * 16 + cq * 4);
        float hv0 = h_s[bq * 516 + k];
        float hv1 = h_s[(bq + 4) * 516 + k];
        unsigned long long hp0 = pack2(hv0, hv0);
        unsigned long long hp1 = pack2(hv1, hv1);
        fma2(acc[0][0], hp0, wv.x);
        fma2(acc[0][1], hp0, wv.y);
        fma2(acc[1][0], hp1, wv.x);
        fma2(acc[1][1], hp1, wv.y);
    }
}

__global__ void __launch_bounds__(256) lstm2_kernel(
    const float* __restrict__ xW0, const float* __restrict__ Wh0,
    const float* __restrict__ Wx1, const float* __restrict__ Wh1,
    const float* __restrict__ b1,
    float* __restrict__ h1g, float* __restrict__ h2g, float* __restrict__ h2rg)
{
    extern __shared__ char smem[];
    float* w_s  = (float*)smem;                      // [1024][16]
    float* h_sB = (float*)(smem + 65536);            // [8][516]
    float* h_sA = (float*)(smem + 82048);            // [8][516]
    float (*red)[128] = (float(*)[128])(smem + 98560); // [16][128]
    float* gs  = (float*)(smem + 106752);
    float* c_s = (float*)(smem + 107264);

    const int tid = threadIdx.x;
    const int L   = blockIdx.x >> 7;
    const int sub = blockIdx.x & 127;
    const uint32_t sbB = smem_u32(h_sB);
    const uint32_t sbA = smem_u32(h_sA);

    const int w    = tid >> 5;
    const int lane = tid & 31;
    const int kp = lane >> 4;
    const int bq = (lane >> 2) & 3;
    const int cq = lane & 3;
    const int ob = (tid >> 4) & 7, oc = tid & 15;   // reduce-thread output mapping (tid<128)
    const int gcol_t = (oc >> 2) * DD + sub * 4 + (oc & 3);

    // ---- load weight slices ----
    if (L == 0) {
        for (int idx = tid; idx < 512 * 16; idx += 256) {
            int k = idx >> 4, c = idx & 15;
            int gcol = (c >> 2) * DD + sub * 4 + (c & 3);
            w_s[idx] = Wh0[(size_t)k * FOURD + gcol];
        }
    } else {
        for (int idx = tid; idx < 512 * 16; idx += 256) {
            int k = idx >> 4, c = idx & 15;
            int gcol = (c >> 2) * DD + sub * 4 + (c & 3);
            w_s[idx]            = Wh1[(size_t)k * FOURD + gcol];
            w_s[512 * 16 + idx] = Wx1[(size_t)k * FOURD + gcol];
        }
    }
    float bias_r = (L == 1 && tid < 128) ? b1[gcol_t] : 0.f;
    if (tid < 32) c_s[tid] = 0.f;
    __syncthreads();

    if (L == 0) {
        // ================= layer 0: 8-warp matvec =================
        for (int t = 0; t < TT; t++) {
            float xwv = 0.f;
            if (tid < 128)
                xwv = xW0[((size_t)(ob * TT + t)) * FOURD + (size_t)gcol_t];

            unsigned long long acc[2][2] = { {0ull,0ull}, {0ull,0ull} };
            if (t > 0) {
                if (tid < 128) { while (ld_acq(&g_prog0[tid]) < t) { } }
                __syncthreads();
                // cp.async h1[t-1] (16KB) -> h_sB, 4 chunks/thread
                #pragma unroll
                for (int i = 0; i < 4; i++) {
                    int idx = tid + i * 256;
                    int b = idx >> 7, cc = idx & 127;
                    cp_async16(sbB + (uint32_t)((b * 516 + cc * 4) * 4),
                               h1g + ((size_t)(b * TT + t - 1)) * DD + cc * 4);
                }
                cp_commit(); cp_wait<0>();
                __syncthreads();
                matvec_sm<32>(w_s, h_sB, w * 64 + kp, cq, bq, acc);
            }

            {
                int rw = w * 2 + kp;   // 0..15
                #pragma unroll
                for (int bi = 0; bi < 2; bi++)
                    #pragma unroll
                    for (int pj = 0; pj < 2; pj++)
                        *(unsigned long long*)&red[rw][(bq + bi*4) * 16 + cq*4 + pj*2] = acc[bi][pj];
            }
            __syncthreads();
            if (tid < 128) {
                float s = xwv;
                #pragma unroll
                for (int r = 0; r < 16; r++) s += red[r][tid];
                gs[tid] = s;
            }
            __syncthreads();

            if (tid < 32) {
                int b = tid >> 2, dd = tid & 3;
                float iv = gs[b*16 + dd],      fv = gs[b*16 + 4 + dd];
                float gv = gs[b*16 + 8 + dd],  ov = gs[b*16 + 12 + dd];
                float ig = 1.f / (1.f + __expf(-iv));
                float fg = 1.f / (1.f + __expf(-fv));
                float gg = tanhf(gv);
                float og = 1.f / (1.f + __expf(-ov));
                float cc = fg * c_s[tid] + ig * gg;
                c_s[tid] = cc;
                float hh = og * tanhf(cc);
                h1g[((size_t)(b * TT + t)) * DD + sub * 4 + dd] = hh;
            }
            __threadfence();
            __syncthreads();
            if (tid == 0) st_rel(&g_prog0[sub], t + 1);
        }
    } else {
        // ================= layer 1: concurrent phase A/B =================
        for (int t = 0; t < TT; t++) {
            if (tid < 128) {
                if (t > 0) { while (ld_acq(&g_prog1[tid]) < t) { } }
            } else {
                while (ld_acq(&g_prog0[tid - 128]) < t + 1) { }
            }
            __syncthreads();

            unsigned long long acc[2][2] = { {0ull,0ull}, {0ull,0ull} };
            if (w < 4) {
                // --- phase B (critical): Wh1 x h2[t-1] ---
                if (t > 0) {
                    #pragma unroll
                    for (int i = 0; i < 8; i++) {
                        int idx = tid + i * 128;
                        int b = idx >> 7, cc = idx & 127;
                        cp_async16(sbB + (uint32_t)((b * 516 + cc * 4) * 4),
                                   h2g + ((size_t)(b * TT + t - 1)) * DD + cc * 4);
                    }
                    cp_commit(); cp_wait<0>();
                    BAR_SYNC(1);
                    matvec_sm<64>(w_s, h_sB, w * 128 + kp, cq, bq, acc);
                }
                int rw = w * 2 + kp;   // 0..7
                #pragma unroll
                for (int bi = 0; bi < 2; bi++)
                    #pragma unroll
                    for (int pj = 0; pj < 2; pj++)
                        *(unsigned long long*)&red[rw][(bq + bi*4) * 16 + cq*4 + pj*2] = acc[bi][pj];
            } else {
                // --- phase A (concurrent): Wx1 x h1[t] ---
                int wa = w - 4;
                #pragma unroll
                for (int i = 0; i < 8; i++) {
                    int idx = (tid - 128) + i * 128;
                    int b = idx >> 7, cc = idx & 127;
                    cp_async16(sbA + (uint32_t)((b * 516 + cc * 4) * 4),
                               h1g + ((size_t)(b * TT + t)) * DD + cc * 4);
                }
                cp_commit(); cp_wait<0>();
                BAR_SYNC(2);
                matvec_sm<64>(w_s + 512 * 16, h_sA, wa * 128 + kp, cq, bq, acc);
                int rw = 8 + wa * 2 + kp;   // 8..15
                #pragma unroll
                for (int bi = 0; bi < 2; bi++)
                    #pragma unroll
                    for (int pj = 0; pj < 2; pj++)
                        *(unsigned long long*)&red[rw][(bq + bi*4) * 16 + cq*4 + pj*2] = acc[bi][pj];
            }
            __syncthreads();   // join phases

            if (tid < 128) {
                float s = bias_r;
                #pragma unroll
                for (int r = 0; r < 16; r++) s += red[r][tid];
                gs[tid] = s;
            }
            __syncthreads();

            if (tid < 32) {
                int b = tid >> 2, dd = tid & 3;
                float iv = gs[b*16 + dd],      fv = gs[b*16 + 4 + dd];
                float gv = gs[b*16 + 8 + dd],  ov = gs[b*16 + 12 + dd];
                float ig = 1.f / (1.f + __expf(-iv));
                float fg = 1.f / (1.f + __expf(-fv));
                float gg = tanhf(gv);
                float og = 1.f / (1.f + __expf(-ov));
                float cc = fg * c_s[tid] + ig * gg;
                c_s[tid] = cc;
                float hh = og * tanhf(cc);
                size_t oidx = ((size_t)(b * TT + t)) * DD + sub * 4 + dd;
                h2g[oidx]  = hh;
                h2rg[oidx] = tf32r(hh);
            }
            __threadfence();
            __syncthreads();
            if (tid == 0) st_rel(&g_prog1[sub], t + 1);
        }
    }
}

// ---------------- launch ----------------
extern "C" void kernel_launch(void* const* d_in, const int* in_sizes, int n_in,
                              void* d_out, int out_size)
{
    const int*   tokens = (const int*)d_in[0];
    const float* emb    = (const float*)d_in[1];
    const float* Wx0    = (const float*)d_in[2];
    const float* Wh0    = (const float*)d_in[3];
    const float* b0     = (const float*)d_in[4];
    const float* Wx1    = (const float*)d_in[5];
    const float* Wh1    = (const float*)d_in[6];
    const float* b1     = (const float*)d_in[7];
    const float* Wout   = (const float*)d_in[8];
    const float* bout   = (const float*)d_in[9];
    float* out = (float*)d_out;

    float *gx, *gxw, *gh1, *gh2, *gh2r, *gwt;
    cudaGetSymbolAddress((void**)&gx,   g_x);
    cudaGetSymbolAddress((void**)&gxw,  g_xW);
    cudaGetSymbolAddress((void**)&gh1,  g_h1);
    cudaGetSymbolAddress((void**)&gh2,  g_h2);
    cudaGetSymbolAddress((void**)&gh2r, g_h2r);
    cudaGetSymbolAddress((void**)&gwt,  g_Wt);

    cudaFuncSetAttribute((const void*)lstm2_kernel,
                         cudaFuncAttributeMaxDynamicSharedMemorySize, LSTM_SMEM);
    cudaFuncSetAttribute((const void*)gemm_mma_kernel,
                         cudaFuncAttributeMaxDynamicSharedMemorySize, GEMM_SMEM);

    // 0) transpose+round Wout -> Wt [V,512]
    transpose_round_kernel<<<dim3(VV / 32, DD / 32), 256>>>(Wout, gwt);
    // 1) embedding + shift (+ progress reset)
    embed_kernel<<<BB * TT, 128>>>(tokens, emb, gx);
    // 2) layer 0 input GEMM: xW0 = x @ Wx0 + b0
    sgemm_f32x2<<<dim3(FOURD / 128, (BB * TT) / 128), 256>>>(gx, Wx0, b0, gxw,
                                                             BB * TT, FOURD, DD);
    // 3) warp-specialized pipelined 2-layer recurrence
    lstm2_kernel<<<2 * NBLK, 256, LSTM_SMEM>>>(gxw, Wh0, Wx1, Wh1, b1,
                                               gh1, gh2, gh2r);
    // 4) logits = h2 @ Wout + bout via mma.sync tf32
    gemm_mma_kernel<<<dim3(VV / 128, (BB * TT) / 128), 256, GEMM_SMEM>>>(
        gh2r, gwt, bout, out);
}